// round 13
// baseline (speedup 1.0000x reference)
#include <cuda_runtime.h>

// Problem constants (fixed shapes from reference)
#define BATCH 4
#define CHAN 16
#define HW (1024 * 1024)
#define NVEC (HW / 4)          // float4 / int4 vectors per image per channel
#define NSEG 513               // labels 0..512, slot 0 = background
#define ACC_PER_IMG (CHAN * NSEG)

// Hybrid split: channels [0, GCH) accumulate via global RED (L2 atomic ALUs),
// channels [GCH, 16) + counts accumulate in shared memory (SM LSU atomic port).
#define GCH 6
#define SCH (CHAN - GCH)       // 10 channels in smem

#define BPI 148                // blocks per image
#define NBLOCKS (BPI * BATCH)  // 592 = 4 blocks/SM * 148 SMs
#define THREADS 512
#define SMEM_FLOATS (2 * SCH * NSEG + NSEG)
#define SMEM_BYTES (SMEM_FLOATS * sizeof(float))  // 43092 B -> 4 blocks/SM

// Global scratch accumulators
__device__ float g_psum[BATCH * ACC_PER_IMG];
__device__ float g_tsum[BATCH * ACC_PER_IMG];
__device__ float g_cnt[BATCH * NSEG];

__global__ void zero_kernel() {
    int n = BATCH * ACC_PER_IMG;
    for (int i = blockIdx.x * blockDim.x + threadIdx.x; i < n;
         i += gridDim.x * blockDim.x) {
        g_psum[i] = 0.0f;
        g_tsum[i] = 0.0f;
        if (i < BATCH * NSEG) g_cnt[i] = 0.0f;
    }
}

__global__ __launch_bounds__(THREADS)
void accum_kernel(const float* __restrict__ pred,
                  const float* __restrict__ target,
                  const int* __restrict__ nuclei) {
    extern __shared__ float sm[];
    float* sp = sm;                      // [SCH][NSEG] pred sums (ch GCH..15)
    float* st = sm + SCH * NSEG;         // [SCH][NSEG] target sums
    float* sc = st + SCH * NSEG;         // [NSEG] counts

    for (int i = threadIdx.x; i < SMEM_FLOATS; i += THREADS) sm[i] = 0.0f;
    __syncthreads();

    const int img = blockIdx.x / BPI;
    const int blk = blockIdx.x % BPI;

    const float4* __restrict__ p4 =
        (const float4*)(pred + (size_t)img * CHAN * HW);
    const float4* __restrict__ t4 =
        (const float4*)(target + (size_t)img * CHAN * HW);
    const int4* __restrict__ n4 = (const int4*)(nuclei + (size_t)img * HW);

    float* __restrict__ gp = g_psum + (size_t)img * ACC_PER_IMG;
    float* __restrict__ gt = g_tsum + (size_t)img * ACC_PER_IMG;

    for (int i = blk * THREADS + threadIdx.x; i < NVEC; i += BPI * THREADS) {
        const int4 lb = n4[i];
        atomicAdd(sc + lb.x, 1.0f);
        atomicAdd(sc + lb.y, 1.0f);
        atomicAdd(sc + lb.z, 1.0f);
        atomicAdd(sc + lb.w, 1.0f);
        // Channels 0..GCH-1: global RED into L2 (fire-and-forget atomics)
#pragma unroll
        for (int c = 0; c < GCH; c++) {
            const float4 v = p4[c * NVEC + i];
            float* bb = gp + c * NSEG;
            atomicAdd(bb + lb.x, v.x);
            atomicAdd(bb + lb.y, v.y);
            atomicAdd(bb + lb.z, v.z);
            atomicAdd(bb + lb.w, v.w);
            const float4 w = t4[c * NVEC + i];
            float* bt = gt + c * NSEG;
            atomicAdd(bt + lb.x, w.x);
            atomicAdd(bt + lb.y, w.y);
            atomicAdd(bt + lb.z, w.z);
            atomicAdd(bt + lb.w, w.w);
        }
        // Channels GCH..15: shared-memory atomics
#pragma unroll
        for (int c = GCH; c < CHAN; c++) {
            const float4 v = p4[c * NVEC + i];
            float* bb = sp + (c - GCH) * NSEG;
            atomicAdd(bb + lb.x, v.x);
            atomicAdd(bb + lb.y, v.y);
            atomicAdd(bb + lb.z, v.z);
            atomicAdd(bb + lb.w, v.w);
            const float4 w = t4[c * NVEC + i];
            float* bt = st + (c - GCH) * NSEG;
            atomicAdd(bt + lb.x, w.x);
            atomicAdd(bt + lb.y, w.y);
            atomicAdd(bt + lb.z, w.z);
            atomicAdd(bt + lb.w, w.w);
        }
    }
    __syncthreads();

    // Flush smem-resident channels + counts to global
    for (int i = threadIdx.x; i < SCH * NSEG; i += THREADS) {
        const int c = i / NSEG + GCH;
        const int s = i % NSEG;
        atomicAdd(gp + c * NSEG + s, sp[i]);
        atomicAdd(gt + c * NSEG + s, st[i]);
    }
    float* gc = g_cnt + (size_t)img * NSEG;
    for (int i = threadIdx.x; i < NSEG; i += THREADS) atomicAdd(gc + i, sc[i]);
}

// Output layout: [pred_means B*512*16][target_means B*512*16][cell_ids B*512]
__global__ void finalize_kernel(float* __restrict__ out) {
    const int idx = blockIdx.x * blockDim.x + threadIdx.x;
    const int total = BATCH * 512 * CHAN;
    if (idx >= total) return;
    const int c = idx % CHAN;
    const int s = (idx / CHAN) % 512;  // segment s -> label s+1
    const int b = idx / (512 * CHAN);

    const float cnt = g_cnt[b * NSEG + s + 1];
    const float denom = fmaxf(cnt, 1.0f);
    out[idx] = g_psum[(size_t)b * ACC_PER_IMG + c * NSEG + s + 1] / denom;
    out[total + idx] =
        g_tsum[(size_t)b * ACC_PER_IMG + c * NSEG + s + 1] / denom;
    if (c == 0)
        out[2 * total + b * 512 + s] = (cnt > 0.0f) ? (float)(s + 1) : 0.0f;
}

extern "C" void kernel_launch(void* const* d_in, const int* in_sizes, int n_in,
                              void* d_out, int out_size) {
    const float* pred = (const float*)d_in[0];
    const float* target = (const float*)d_in[1];
    const int* nuclei = (const int*)d_in[2];
    float* out = (float*)d_out;

    zero_kernel<<<128, 256>>>();
    accum_kernel<<<NBLOCKS, THREADS, SMEM_BYTES>>>(pred, target, nuclei);
    const int total = BATCH * 512 * CHAN;
    finalize_kernel<<<(total + 255) / 256, 256>>>(out);
}

// round 15
// speedup vs baseline: 3.5087x; 3.5087x over previous
#include <cuda_runtime.h>

// Problem constants (fixed shapes from reference)
#define BATCH 4
#define CHAN 16
#define HW (1024 * 1024)
#define NVEC (HW / 4)          // float4 / int4 vectors per image per channel
#define NSEG 513               // labels 0..512, slot 0 = background
#define ACC_PER_IMG (CHAN * NSEG)
#define BPI 111                // blocks per image
#define NBLOCKS (BPI * BATCH)  // 444 total
#define THREADS 512
#define SMEM_BYTES ((2 * ACC_PER_IMG + NSEG) * sizeof(float))  // ~66.1 KB

// Global scratch accumulators (allocation-free rule: __device__ globals)
__device__ float g_psum[BATCH * ACC_PER_IMG];
__device__ float g_tsum[BATCH * ACC_PER_IMG];
__device__ float g_cnt[BATCH * NSEG];

__global__ void zero_kernel() {
    int n = BATCH * ACC_PER_IMG;
    for (int i = blockIdx.x * blockDim.x + threadIdx.x; i < n;
         i += gridDim.x * blockDim.x) {
        g_psum[i] = 0.0f;
        g_tsum[i] = 0.0f;
        if (i < BATCH * NSEG) g_cnt[i] = 0.0f;
    }
}

__global__ __launch_bounds__(THREADS)
void accum_kernel(const float* __restrict__ pred,
                  const float* __restrict__ target,
                  const int* __restrict__ nuclei) {
    extern __shared__ float sm[];
    float* sp = sm;                      // [CHAN][NSEG] pred sums
    float* st = sm + ACC_PER_IMG;        // [CHAN][NSEG] target sums
    float* sc = st + ACC_PER_IMG;        // [NSEG] counts

    for (int i = threadIdx.x; i < 2 * ACC_PER_IMG + NSEG; i += THREADS)
        sm[i] = 0.0f;
    __syncthreads();

    const int img = blockIdx.x / BPI;
    const int blk = blockIdx.x % BPI;

    const float4* __restrict__ p4 =
        (const float4*)(pred + (size_t)img * CHAN * HW);
    const float4* __restrict__ t4 =
        (const float4*)(target + (size_t)img * CHAN * HW);
    const int4* __restrict__ n4 = (const int4*)(nuclei + (size_t)img * HW);

    for (int i = blk * THREADS + threadIdx.x; i < NVEC; i += BPI * THREADS) {
        const int4 lb = n4[i];
        atomicAdd(sc + lb.x, 1.0f);
        atomicAdd(sc + lb.y, 1.0f);
        atomicAdd(sc + lb.z, 1.0f);
        atomicAdd(sc + lb.w, 1.0f);
#pragma unroll
        for (int c = 0; c < CHAN; c++) {
            const float4 v = p4[c * NVEC + i];
            float* bb = sp + c * NSEG;
            atomicAdd(bb + lb.x, v.x);
            atomicAdd(bb + lb.y, v.y);
            atomicAdd(bb + lb.z, v.z);
            atomicAdd(bb + lb.w, v.w);
            const float4 w = t4[c * NVEC + i];
            float* bt = st + c * NSEG;
            atomicAdd(bt + lb.x, w.x);
            atomicAdd(bt + lb.y, w.y);
            atomicAdd(bt + lb.z, w.z);
            atomicAdd(bt + lb.w, w.w);
        }
    }
    __syncthreads();

    // Flush block-private accumulators to global
    float* gp = g_psum + (size_t)img * ACC_PER_IMG;
    float* gt = g_tsum + (size_t)img * ACC_PER_IMG;
    for (int i = threadIdx.x; i < ACC_PER_IMG; i += THREADS) {
        atomicAdd(gp + i, sp[i]);
        atomicAdd(gt + i, st[i]);
    }
    float* gc = g_cnt + (size_t)img * NSEG;
    for (int i = threadIdx.x; i < NSEG; i += THREADS) atomicAdd(gc + i, sc[i]);
}

// Output layout: [pred_means (B*512*16)] [target_means (B*512*16)] [cell_ids (B*512)]
__global__ void finalize_kernel(float* __restrict__ out) {
    const int idx = blockIdx.x * blockDim.x + threadIdx.x;
    const int total = BATCH * 512 * CHAN;
    if (idx >= total) return;
    const int c = idx % CHAN;
    const int s = (idx / CHAN) % 512;   // segment 0..511 -> label s+1
    const int b = idx / (512 * CHAN);

    const float cnt = g_cnt[b * NSEG + s + 1];
    const float denom = fmaxf(cnt, 1.0f);
    const float ps = g_psum[(size_t)b * ACC_PER_IMG + c * NSEG + s + 1];
    const float ts = g_tsum[(size_t)b * ACC_PER_IMG + c * NSEG + s + 1];

    out[idx] = ps / denom;
    out[total + idx] = ts / denom;
    if (c == 0)
        out[2 * total + b * 512 + s] = (cnt > 0.0f) ? (float)(s + 1) : 0.0f;
}

extern "C" void kernel_launch(void* const* d_in, const int* in_sizes, int n_in,
                              void* d_out, int out_size) {
    const float* pred = (const float*)d_in[0];
    const float* target = (const float*)d_in[1];
    const int* nuclei = (const int*)d_in[2];
    float* out = (float*)d_out;

    cudaFuncSetAttribute(accum_kernel,
                         cudaFuncAttributeMaxDynamicSharedMemorySize,
                         (int)SMEM_BYTES);

    zero_kernel<<<64, 256>>>();
    accum_kernel<<<NBLOCKS, THREADS, SMEM_BYTES>>>(pred, target, nuclei);
    const int total = BATCH * 512 * CHAN;
    finalize_kernel<<<(total + 255) / 256, 256>>>(out);
}